// round 5
// baseline (speedup 1.0000x reference)
#include <cuda_runtime.h>
#include <cuda_bf16.h>
#include <cstdint>

// DeterministicLattice: ring-stencil fusion + 5-output "GenesisGeometry" engine.
// fused f = (phi*x[i] + x[i-1] + x[i+1]) / (phi + 2), ring on axis 0.
// planes: [f + tanh(f)/phi, tanh(phi f), sigmoid(phi f),
//          sin(f)cos(phi f), f*exp(-|f|/phi)]
//
// R5 (= R4 retry; prior run died to infra): each thread owns 4 CONSECUTIVE
// float4s (64B). 4 | 128 items/row, so a thread never straddles a row
// boundary -> one neighbor-row computation per thread, and each warp's
// per-plane store run is a contiguous 2KB burst (vs 512B) to improve HBM
// page locality on the 5 write streams.

#define PHI_F      1.6180339887498949f
#define INVPHI_F   0.6180339887498949f
#define INV_PHI2_F 0.2763932022500210f  // 1/(PHI+2)

#define VPR_LOG2   7      // 128 float4 per row (DIM=512)
#define VPR_MASK   127

__device__ __forceinline__ void genesis_engine(float f,
                                               float& idn, float& bl,
                                               float& cr,  float& tr,
                                               float& sp)
{
    const float g   = fabsf(f);
    const float sgn = copysignf(1.0f, f);

    const float Ea = __expf(PHI_F * g);        // e^{phi g}
    const float ca = __expf(-INVPHI_F * g);    // e^{-g/phi}

    const float E2 = Ea * Ea;                  // e^{2 phi g}
    const float eg = Ea * ca;                  // e^{g}   (phi - 1/phi = 1)
    const float q2 = eg * eg;                  // e^{2g}

    const float A = q2 + 1.0f;
    const float B = E2 + 1.0f;
    const float C = Ea + 1.0f;

    const float r  = __fdividef(1.0f, A * B * C);   // one RCP for 3 denoms
    const float rA = B * C * r;
    const float rB = A * C * r;
    const float rC = A * B * r;

    const float t = (q2 - 1.0f) * rA * sgn;    // tanh(f)
    bl = (E2 - 1.0f) * rB * sgn;               // tanh(phi f)
    const float s = Ea * rC;                   // sigmoid(phi g)
    cr = (f >= 0.0f) ? s : (1.0f - s);         // sigmoid(phi f)

    idn = fmaf(INVPHI_F, t, f);
    tr  = __sinf(f) * __cosf(PHI_F * f);
    sp  = f * ca;
}

__global__ void __launch_bounds__(256)
DeterministicLattice_43508018709032_kernel(const float4* __restrict__ xv,
                                           float4* __restrict__ ov,
                                           int nrows)
{
    const int total4 = nrows << VPR_LOG2;
    // Each thread: 4 consecutive float4s starting at idx0 (idx0 % 4 == 0).
    const int idx0 = (blockIdx.x * 256 + threadIdx.x) * 4;
    if (idx0 >= total4) return;

    const int row  = idx0 >> VPR_LOG2;
    const int col  = idx0 & VPR_MASK;          // multiple of 4, <= 124
    const int mask = nrows - 1;                // nrows is a power of two
    const int lbase = (((row - 1) & mask) << VPR_LOG2) + col;
    const int rbase = (((row + 1) & mask) << VPR_LOG2) + col;

    // Front-batch all 12 loads (MLP=12/thread)
    float4 s[4], l[4], r[4];
#pragma unroll
    for (int k = 0; k < 4; ++k) {
        s[k] = xv[idx0 + k];
        l[k] = xv[lbase + k];
        r[k] = xv[rbase + k];
    }

#pragma unroll
    for (int k = 0; k < 4; ++k) {
        const float fs[4] = { s[k].x, s[k].y, s[k].z, s[k].w };
        const float fl[4] = { l[k].x, l[k].y, l[k].z, l[k].w };
        const float fr[4] = { r[k].x, r[k].y, r[k].z, r[k].w };

        float4 o_idn, o_bl, o_cr, o_tr, o_sp;
        float* pi = &o_idn.x; float* pb = &o_bl.x; float* pc = &o_cr.x;
        float* pt = &o_tr.x;  float* ps = &o_sp.x;

#pragma unroll
        for (int j = 0; j < 4; ++j) {
            const float f = (fmaf(PHI_F, fs[j], fl[j]) + fr[j]) * INV_PHI2_F;
            genesis_engine(f, pi[j], pb[j], pc[j], pt[j], ps[j]);
        }

        const int idx = idx0 + k;
        __stcs(ov + 0 * total4 + idx, o_idn);
        __stcs(ov + 1 * total4 + idx, o_bl);
        __stcs(ov + 2 * total4 + idx, o_cr);
        __stcs(ov + 3 * total4 + idx, o_tr);
        __stcs(ov + 4 * total4 + idx, o_sp);
    }
}

extern "C" void kernel_launch(void* const* d_in, const int* in_sizes, int n_in,
                              void* d_out, int out_size)
{
    const float4* x = (const float4*)d_in[0];
    float4* out = (float4*)d_out;

    const int DIM    = 512;
    const int nrows  = in_sizes[0] / DIM;       // 65536
    const int total4 = nrows * (DIM / 4);       // 8,388,608

    const int threads = 256;
    const int items_per_block = threads * 4;    // 1024 float4 per block
    const int blocks = (total4 + items_per_block - 1) / items_per_block;
    DeterministicLattice_43508018709032_kernel<<<blocks, threads>>>(x, out, nrows);
}